// round 3
// baseline (speedup 1.0000x reference)
#include <cuda_runtime.h>
#include <cstdint>
#include <cstddef>

#define N_NODES     100000
#define DIM         256
#define N_ET        6
#define M_PER_TYPE  400000
#define TOTAL_EDGES (N_ET * M_PER_TYPE)
#define NBIG        (N_ET * DIM)      /* 1536 */
#define POS_TAB     512

// ---------------- device scratch (sanctioned: __device__ globals) ----------
__device__ float g_prop[(size_t)N_NODES * NBIG];   // 614.4 MB
__device__ float g_gating[POS_TAB * DIM];          // 512 KB
__device__ int   g_bin[N_NODES];

// ---------------- gating: pos_gating = 2*sigmoid(pos_emb @ Wp^T + bp) ------
__global__ void gating_kernel(const float* __restrict__ Wp,
                              const float* __restrict__ bp) {
    __shared__ float emb[DIM];
    const int p = blockIdx.x;
    const int t = threadIdx.x;
    if (t < 127) {
        float y    = (float)(2 * t) / 254.0f;
        float invf = 1.0f / powf(10000.0f, y);
        float ang  = (float)p * invf;
        emb[t]       = sinf(ang);
        emb[t + 127] = cosf(ang);
    } else if (t >= 254) {
        emb[t] = 0.0f;
    }
    // piggyback: zero bincount (512*256 = 131072 threads >= N_NODES)
    int bi = blockIdx.x * blockDim.x + t;
    if (bi < N_NODES) g_bin[bi] = 0;
    __syncthreads();

    float s = bp[t];
    const float* w = Wp + (size_t)t * DIM;
#pragma unroll 8
    for (int k = 0; k < DIM; ++k) s += emb[k] * w[k];
    g_gating[p * DIM + t] = 2.0f / (1.0f + expf(-s));
}

// ---------------- GEMM: prop = node_states @ W^T + b (3xTF32 mma) ----------
__device__ __forceinline__ unsigned f2tf(float x) {
    unsigned r;
    asm("cvt.rna.tf32.f32 %0, %1;" : "=r"(r) : "f"(x));
    return r;
}
__device__ __forceinline__ void mma8(float* d, const unsigned* a, const unsigned* b) {
    asm volatile(
        "mma.sync.aligned.m16n8k8.row.col.f32.tf32.tf32.f32 "
        "{%0,%1,%2,%3}, {%4,%5,%6,%7}, {%8,%9}, {%0,%1,%2,%3};"
        : "+f"(d[0]), "+f"(d[1]), "+f"(d[2]), "+f"(d[3])
        : "r"(a[0]), "r"(a[1]), "r"(a[2]), "r"(a[3]), "r"(b[0]), "r"(b[1]));
}

__global__ __launch_bounds__(256, 2)
void gemm_kernel(const float* __restrict__ A, const float* __restrict__ W,
                 const float* __restrict__ bias) {
    __shared__ float As[128][36];   // pad 36 -> conflict-free frag loads
    __shared__ float Bs[64][36];
    const int tid  = threadIdx.x;
    const int lane = tid & 31;
    const int wid  = tid >> 5;
    const int wm   = (wid & 3) * 32;   // warp row base within 128
    const int wn   = (wid >> 2) * 32;  // warp col base within 64
    const int mBase = blockIdx.y * 128;
    const int nBase = blockIdx.x * 64;

    float acc[2][4][4];
#pragma unroll
    for (int i = 0; i < 2; i++)
#pragma unroll
        for (int j = 0; j < 4; j++)
#pragma unroll
            for (int k = 0; k < 4; k++) acc[i][j][k] = 0.f;

    for (int k0 = 0; k0 < DIM; k0 += 32) {
#pragma unroll
        for (int i = tid; i < 128 * 8; i += 256) {
            int row = i >> 3, kv = (i & 7) * 4;
            int gr = mBase + row;
            float4 v = make_float4(0.f, 0.f, 0.f, 0.f);
            if (gr < N_NODES)
                v = *reinterpret_cast<const float4*>(A + (size_t)gr * DIM + k0 + kv);
            *reinterpret_cast<float4*>(&As[row][kv]) = v;
        }
#pragma unroll
        for (int i = tid; i < 64 * 8; i += 256) {
            int row = i >> 3, kv = (i & 7) * 4;
            float4 v = *reinterpret_cast<const float4*>(W + (size_t)(nBase + row) * DIM + k0 + kv);
            *reinterpret_cast<float4*>(&Bs[row][kv]) = v;
        }
        __syncthreads();

#pragma unroll
        for (int kk = 0; kk < 32; kk += 8) {
            unsigned ahi[2][4], alo[2][4];
#pragma unroll
            for (int mt = 0; mt < 2; mt++) {
                int r0 = wm + mt * 16 + (lane >> 2);
                int c0 = kk + (lane & 3);
                float vv[4];
                vv[0] = As[r0][c0];     vv[1] = As[r0 + 8][c0];
                vv[2] = As[r0][c0 + 4]; vv[3] = As[r0 + 8][c0 + 4];
#pragma unroll
                for (int j = 0; j < 4; j++) {
                    unsigned h = f2tf(vv[j]);
                    ahi[mt][j] = h;
                    alo[mt][j] = f2tf(vv[j] - __uint_as_float(h));
                }
            }
            unsigned bhi[4][2], blo[4][2];
#pragma unroll
            for (int nt = 0; nt < 4; nt++) {
                int r0 = wn + nt * 8 + (lane >> 2);
                int c0 = kk + (lane & 3);
                float v0 = Bs[r0][c0], v1 = Bs[r0][c0 + 4];
                unsigned h0 = f2tf(v0), h1 = f2tf(v1);
                bhi[nt][0] = h0; bhi[nt][1] = h1;
                blo[nt][0] = f2tf(v0 - __uint_as_float(h0));
                blo[nt][1] = f2tf(v1 - __uint_as_float(h1));
            }
#pragma unroll
            for (int mt = 0; mt < 2; mt++)
#pragma unroll
                for (int nt = 0; nt < 4; nt++) {
                    mma8(acc[mt][nt], ahi[mt], bhi[nt]);  // hi*hi
                    mma8(acc[mt][nt], ahi[mt], blo[nt]);  // hi*lo
                    mma8(acc[mt][nt], alo[mt], bhi[nt]);  // lo*hi
                }
        }
        __syncthreads();
    }

    // epilogue: +bias, store fp32
#pragma unroll
    for (int mt = 0; mt < 2; mt++) {
#pragma unroll
        for (int nt = 0; nt < 4; nt++) {
            int row = mBase + wm + mt * 16 + (lane >> 2);
            int col = nBase + wn + nt * 8 + 2 * (lane & 3);
            float b0 = bias[col], b1 = bias[col + 1];
            if (row < N_NODES) {
                float2 v = make_float2(acc[mt][nt][0] + b0, acc[mt][nt][1] + b1);
                *reinterpret_cast<float2*>(&g_prop[(size_t)row * NBIG + col]) = v;
            }
            if (row + 8 < N_NODES) {
                float2 v = make_float2(acc[mt][nt][2] + b0, acc[mt][nt][3] + b1);
                *reinterpret_cast<float2*>(&g_prop[(size_t)(row + 8) * NBIG + col]) = v;
            }
        }
    }
}

// ---------------- scatter: one warp per edge, vector f32 reductions --------
// NOTE: edge/pos indices are int32 (JAX x64 disabled -> int64 request silently
// becomes int32). Reading them as int64 was the round-2 illegal-access bug.
__global__ void scatter_kernel(const int* __restrict__ edges,
                               const int* __restrict__ posl,
                               float* __restrict__ out) {
    int e    = (blockIdx.x * blockDim.x + threadIdx.x) >> 5;
    int lane = threadIdx.x & 31;
    if (e >= TOTAL_EDGES) return;

    int type = e / M_PER_TYPE;
    int src = edges[(size_t)2 * e];
    int tgt = edges[(size_t)2 * e + 1];
    int pos = posl[e];

    const float4* __restrict__ p = reinterpret_cast<const float4*>(
                          g_prop + (size_t)src * NBIG + type * DIM) + lane * 2;
    const float4* g = reinterpret_cast<const float4*>(
                          g_gating + (size_t)pos * DIM) + lane * 2;
    float4 p0 = p[0], p1 = p[1];
    float4 g0 = __ldg(g), g1 = __ldg(g + 1);
    float4 m0 = make_float4(p0.x * g0.x, p0.y * g0.y, p0.z * g0.z, p0.w * g0.w);
    float4 m1 = make_float4(p1.x * g1.x, p1.y * g1.y, p1.z * g1.z, p1.w * g1.w);

    float* dst = out + (size_t)tgt * DIM + lane * 8;
    asm volatile("red.global.add.v4.f32 [%0], {%1,%2,%3,%4};"
                 :: "l"(dst), "f"(m0.x), "f"(m0.y), "f"(m0.z), "f"(m0.w) : "memory");
    asm volatile("red.global.add.v4.f32 [%0], {%1,%2,%3,%4};"
                 :: "l"(dst + 4), "f"(m1.x), "f"(m1.y), "f"(m1.z), "f"(m1.w) : "memory");
    if (lane == 0) atomicAdd(&g_bin[tgt], 1);
}

// ---------------- divide by degree -----------------------------------------
__global__ void divide_kernel(float* __restrict__ out) {
    int idx = blockIdx.x * blockDim.x + threadIdx.x;
    const int total4 = N_NODES * DIM / 4;
    if (idx >= total4) return;
    int row = idx >> 6;                 // 64 float4 per 256-float row
    int cnt = g_bin[row];
    float div = (cnt == 0) ? 1.0f : (float)cnt;
    float s = 1.0f / (div + 1e-8f);
    float4* o4 = reinterpret_cast<float4*>(out);
    float4 v = o4[idx];
    v.x *= s; v.y *= s; v.z *= s; v.w *= s;
    o4[idx] = v;
}

// ---------------- launch ----------------------------------------------------
extern "C" void kernel_launch(void* const* d_in, const int* in_sizes, int n_in,
                              void* d_out, int out_size) {
    const float* node_states = (const float*)d_in[0];
    const float* W    = (const float*)d_in[1];
    const float* b    = (const float*)d_in[2];
    const float* Wp   = (const float*)d_in[3];
    const float* bp   = (const float*)d_in[4];
    const int*   edges = (const int*)d_in[5];
    const int*   posl  = (const int*)d_in[6];
    float* out = (float*)d_out;

    cudaMemsetAsync(out, 0, (size_t)out_size * sizeof(float));

    gating_kernel<<<POS_TAB, 256>>>(Wp, bp);

    dim3 gg(NBIG / 64, (N_NODES + 127) / 128);
    gemm_kernel<<<gg, 256>>>(node_states, W, b);

    scatter_kernel<<<(TOTAL_EDGES + 7) / 8, 256>>>(edges, posl, out);

    divide_kernel<<<(N_NODES * DIM / 4 + 255) / 256, 256>>>(out);
}

// round 5
// speedup vs baseline: 1.2566x; 1.2566x over previous
#include <cuda_runtime.h>
#include <cuda_bf16.h>
#include <cstdint>
#include <cstddef>

#define N_NODES     100000
#define DIM         256
#define N_ET        6
#define M_PER_TYPE  400000
#define TOTAL_EDGES (N_ET * M_PER_TYPE)
#define NBIG        (N_ET * DIM)      /* 1536 */
#define POS_TAB     512

// ---------------- device scratch (sanctioned: __device__ globals) ----------
__device__ float g_prop[(size_t)N_NODES * NBIG];   // 614.4 MB
__device__ float g_gating[POS_TAB * DIM];          // 512 KB
__device__ int   g_bin[N_NODES];

// ---------------- gating: pos_gating = 2*sigmoid(pos_emb @ Wp^T + bp) ------
__global__ void gating_kernel(const float* __restrict__ Wp,
                              const float* __restrict__ bp) {
    __shared__ float emb[DIM];
    const int p = blockIdx.x;
    const int t = threadIdx.x;
    if (t < 127) {
        float y    = (float)(2 * t) / 254.0f;
        float invf = 1.0f / powf(10000.0f, y);
        float ang  = (float)p * invf;
        emb[t]       = sinf(ang);
        emb[t + 127] = cosf(ang);
    } else if (t >= 254) {
        emb[t] = 0.0f;
    }
    // piggyback: zero bincount (512*256 threads >= N_NODES)
    int bi = blockIdx.x * blockDim.x + t;
    if (bi < N_NODES) g_bin[bi] = 0;
    __syncthreads();

    float s = bp[t];
    const float* w = Wp + (size_t)t * DIM;
#pragma unroll 8
    for (int k = 0; k < DIM; ++k) s += emb[k] * w[k];
    g_gating[p * DIM + t] = 2.0f / (1.0f + expf(-s));
}

// ---------------- GEMM: prop = node_states @ W^T + b (3x bf16 mma) ---------
__device__ __forceinline__ void split_pack(float x, float y,
                                           uint32_t& hi, uint32_t& lo) {
    __nv_bfloat16 hx = __float2bfloat16_rn(x);
    __nv_bfloat16 hy = __float2bfloat16_rn(y);
    __nv_bfloat16 lx = __float2bfloat16_rn(x - __bfloat162float(hx));
    __nv_bfloat16 ly = __float2bfloat16_rn(y - __bfloat162float(hy));
    hi = ((uint32_t)__bfloat16_as_ushort(hy) << 16) | __bfloat16_as_ushort(hx);
    lo = ((uint32_t)__bfloat16_as_ushort(ly) << 16) | __bfloat16_as_ushort(lx);
}

__device__ __forceinline__ void mma16(float* d, const uint32_t* a, const uint32_t* b) {
    asm volatile(
        "mma.sync.aligned.m16n8k16.row.col.f32.bf16.bf16.f32 "
        "{%0,%1,%2,%3}, {%4,%5,%6,%7}, {%8,%9}, {%0,%1,%2,%3};"
        : "+f"(d[0]), "+f"(d[1]), "+f"(d[2]), "+f"(d[3])
        : "r"(a[0]), "r"(a[1]), "r"(a[2]), "r"(a[3]), "r"(b[0]), "r"(b[1]));
}

__global__ __launch_bounds__(256, 2)
void gemm_kernel(const float* __restrict__ A, const float* __restrict__ W,
                 const float* __restrict__ bias) {
    // bf16 hi/lo tiles, K-chunk = 32, pad 40 -> conflict-free b32 frag loads
    __shared__ __nv_bfloat16 Ah[128][40], Al[128][40];
    __shared__ __nv_bfloat16 Bh[64][40],  Bl[64][40];
    const int tid  = threadIdx.x;
    const int lane = tid & 31;
    const int wid  = tid >> 5;
    const int wm   = (wid & 3) * 32;   // warp row base within 128
    const int wn   = (wid >> 2) * 32;  // warp col base within 64
    const int mBase = blockIdx.y * 128;
    const int nBase = blockIdx.x * 64;

    float acc[2][4][4];
#pragma unroll
    for (int i = 0; i < 2; i++)
#pragma unroll
        for (int j = 0; j < 4; j++)
#pragma unroll
            for (int k = 0; k < 4; k++) acc[i][j][k] = 0.f;

    for (int k0 = 0; k0 < DIM; k0 += 32) {
        // ---- stage A (128 x 32) with bf16 hi/lo split
#pragma unroll
        for (int i = tid; i < 128 * 8; i += 256) {
            int r = i >> 3, c4 = (i & 7) * 4;
            int gr = mBase + r;
            float4 v = make_float4(0.f, 0.f, 0.f, 0.f);
            if (gr < N_NODES)
                v = *reinterpret_cast<const float4*>(A + (size_t)gr * DIM + k0 + c4);
            uint32_t h01, l01, h23, l23;
            split_pack(v.x, v.y, h01, l01);
            split_pack(v.z, v.w, h23, l23);
            *reinterpret_cast<uint32_t*>(&Ah[r][c4])     = h01;
            *reinterpret_cast<uint32_t*>(&Ah[r][c4 + 2]) = h23;
            *reinterpret_cast<uint32_t*>(&Al[r][c4])     = l01;
            *reinterpret_cast<uint32_t*>(&Al[r][c4 + 2]) = l23;
        }
        // ---- stage B (64 x 32)
#pragma unroll
        for (int i = tid; i < 64 * 8; i += 256) {
            int r = i >> 3, c4 = (i & 7) * 4;
            float4 v = *reinterpret_cast<const float4*>(
                W + (size_t)(nBase + r) * DIM + k0 + c4);
            uint32_t h01, l01, h23, l23;
            split_pack(v.x, v.y, h01, l01);
            split_pack(v.z, v.w, h23, l23);
            *reinterpret_cast<uint32_t*>(&Bh[r][c4])     = h01;
            *reinterpret_cast<uint32_t*>(&Bh[r][c4 + 2]) = h23;
            *reinterpret_cast<uint32_t*>(&Bl[r][c4])     = l01;
            *reinterpret_cast<uint32_t*>(&Bl[r][c4 + 2]) = l23;
        }
        __syncthreads();

#pragma unroll
        for (int kk = 0; kk < 32; kk += 16) {
            const int cA = kk + (lane & 3) * 2;
            uint32_t ah[2][4], al[2][4];
#pragma unroll
            for (int mt = 0; mt < 2; mt++) {
                int r0 = wm + mt * 16 + (lane >> 2);
                ah[mt][0] = *reinterpret_cast<const uint32_t*>(&Ah[r0][cA]);
                ah[mt][1] = *reinterpret_cast<const uint32_t*>(&Ah[r0 + 8][cA]);
                ah[mt][2] = *reinterpret_cast<const uint32_t*>(&Ah[r0][cA + 8]);
                ah[mt][3] = *reinterpret_cast<const uint32_t*>(&Ah[r0 + 8][cA + 8]);
                al[mt][0] = *reinterpret_cast<const uint32_t*>(&Al[r0][cA]);
                al[mt][1] = *reinterpret_cast<const uint32_t*>(&Al[r0 + 8][cA]);
                al[mt][2] = *reinterpret_cast<const uint32_t*>(&Al[r0][cA + 8]);
                al[mt][3] = *reinterpret_cast<const uint32_t*>(&Al[r0 + 8][cA + 8]);
            }
            uint32_t bh[4][2], bl[4][2];
#pragma unroll
            for (int nt = 0; nt < 4; nt++) {
                int n0 = wn + nt * 8 + (lane >> 2);
                bh[nt][0] = *reinterpret_cast<const uint32_t*>(&Bh[n0][cA]);
                bh[nt][1] = *reinterpret_cast<const uint32_t*>(&Bh[n0][cA + 8]);
                bl[nt][0] = *reinterpret_cast<const uint32_t*>(&Bl[n0][cA]);
                bl[nt][1] = *reinterpret_cast<const uint32_t*>(&Bl[n0][cA + 8]);
            }
#pragma unroll
            for (int mt = 0; mt < 2; mt++)
#pragma unroll
                for (int nt = 0; nt < 4; nt++) {
                    mma16(acc[mt][nt], ah[mt], bh[nt]);  // hi*hi
                    mma16(acc[mt][nt], ah[mt], bl[nt]);  // hi*lo
                    mma16(acc[mt][nt], al[mt], bh[nt]);  // lo*hi
                }
        }
        __syncthreads();
    }

    // ---- epilogue: +bias, store fp32
#pragma unroll
    for (int mt = 0; mt < 2; mt++) {
#pragma unroll
        for (int nt = 0; nt < 4; nt++) {
            int row = mBase + wm + mt * 16 + (lane >> 2);
            int col = nBase + wn + nt * 8 + 2 * (lane & 3);
            float b0 = bias[col], b1 = bias[col + 1];
            if (row < N_NODES) {
                float2 v = make_float2(acc[mt][nt][0] + b0, acc[mt][nt][1] + b1);
                *reinterpret_cast<float2*>(&g_prop[(size_t)row * NBIG + col]) = v;
            }
            if (row + 8 < N_NODES) {
                float2 v = make_float2(acc[mt][nt][2] + b0, acc[mt][nt][3] + b1);
                *reinterpret_cast<float2*>(&g_prop[(size_t)(row + 8) * NBIG + col]) = v;
            }
        }
    }
}

// ---------------- scatter: one warp per edge, vector f32 reductions --------
// NOTE: edge/pos indices are int32 (JAX x64 disabled).
__global__ void scatter_kernel(const int* __restrict__ edges,
                               const int* __restrict__ posl,
                               float* __restrict__ out) {
    int e    = (blockIdx.x * blockDim.x + threadIdx.x) >> 5;
    int lane = threadIdx.x & 31;
    if (e >= TOTAL_EDGES) return;

    int type = e / M_PER_TYPE;
    int src = edges[(size_t)2 * e];
    int tgt = edges[(size_t)2 * e + 1];
    int pos = posl[e];

    const float4* __restrict__ p = reinterpret_cast<const float4*>(
                          g_prop + (size_t)src * NBIG + type * DIM) + lane * 2;
    const float4* g = reinterpret_cast<const float4*>(
                          g_gating + (size_t)pos * DIM) + lane * 2;
    float4 p0 = p[0], p1 = p[1];
    float4 g0 = __ldg(g), g1 = __ldg(g + 1);
    float4 m0 = make_float4(p0.x * g0.x, p0.y * g0.y, p0.z * g0.z, p0.w * g0.w);
    float4 m1 = make_float4(p1.x * g1.x, p1.y * g1.y, p1.z * g1.z, p1.w * g1.w);

    float* dst = out + (size_t)tgt * DIM + lane * 8;
    asm volatile("red.global.add.v4.f32 [%0], {%1,%2,%3,%4};"
                 :: "l"(dst), "f"(m0.x), "f"(m0.y), "f"(m0.z), "f"(m0.w) : "memory");
    asm volatile("red.global.add.v4.f32 [%0], {%1,%2,%3,%4};"
                 :: "l"(dst + 4), "f"(m1.x), "f"(m1.y), "f"(m1.z), "f"(m1.w) : "memory");
    if (lane == 0) atomicAdd(&g_bin[tgt], 1);
}

// ---------------- divide by degree -----------------------------------------
__global__ void divide_kernel(float* __restrict__ out) {
    int idx = blockIdx.x * blockDim.x + threadIdx.x;
    const int total4 = N_NODES * DIM / 4;
    if (idx >= total4) return;
    int row = idx >> 6;
    int cnt = g_bin[row];
    float div = (cnt == 0) ? 1.0f : (float)cnt;
    float s = 1.0f / (div + 1e-8f);
    float4* o4 = reinterpret_cast<float4*>(out);
    float4 v = o4[idx];
    v.x *= s; v.y *= s; v.z *= s; v.w *= s;
    o4[idx] = v;
}

// ---------------- launch ----------------------------------------------------
extern "C" void kernel_launch(void* const* d_in, const int* in_sizes, int n_in,
                              void* d_out, int out_size) {
    const float* node_states = (const float*)d_in[0];
    const float* W    = (const float*)d_in[1];
    const float* b    = (const float*)d_in[2];
    const float* Wp   = (const float*)d_in[3];
    const float* bp   = (const float*)d_in[4];
    const int*   edges = (const int*)d_in[5];
    const int*   posl  = (const int*)d_in[6];
    float* out = (float*)d_out;

    cudaMemsetAsync(out, 0, (size_t)out_size * sizeof(float));

    gating_kernel<<<POS_TAB, 256>>>(Wp, bp);

    dim3 gg(NBIG / 64, (N_NODES + 127) / 128);
    gemm_kernel<<<gg, 256>>>(node_states, W, b);

    scatter_kernel<<<(TOTAL_EDGES + 7) / 8, 256>>>(edges, posl, out);

    divide_kernel<<<(N_NODES * DIM / 4 + 255) / 256, 256>>>(out);
}

// round 6
// speedup vs baseline: 1.5218x; 1.2110x over previous
#include <cuda_runtime.h>
#include <cuda_bf16.h>
#include <cstdint>
#include <cstddef>

#define N_NODES     100000
#define DIM         256
#define N_ET        6
#define M_PER_TYPE  400000
#define TOTAL_EDGES (N_ET * M_PER_TYPE)
#define NBIG        (N_ET * DIM)      /* 1536 */
#define POS_TAB     512
#define SCAN_T      1024
#define SCAN_CHUNK  98               /* 1024*98 = 100352 >= N_NODES */
#define CNT_PAD     (SCAN_T * SCAN_CHUNK)

// ---------------- device scratch (sanctioned: __device__ globals) ----------
__device__ float    g_prop[(size_t)N_NODES * NBIG];   // 614.4 MB
__device__ float    g_gating[POS_TAB * DIM];          // 512 KB
__device__ int      g_cnt[CNT_PAD];                   // per-target degree
__device__ int      g_off[N_NODES + 1];               // CSR offsets
__device__ int      g_cur[N_NODES];                   // placement cursors
__device__ uint32_t g_sorted[TOTAL_EDGES];            // packed src/type/pos (9.6MB)

// ---------------- gating + zero counters ------------------------------------
__global__ void gating_kernel(const float* __restrict__ Wp,
                              const float* __restrict__ bp) {
    __shared__ float emb[DIM];
    const int p = blockIdx.x;
    const int t = threadIdx.x;
    if (t < 127) {
        float y    = (float)(2 * t) / 254.0f;
        float invf = 1.0f / powf(10000.0f, y);
        float ang  = (float)p * invf;
        emb[t]       = sinf(ang);
        emb[t + 127] = cosf(ang);
    } else if (t >= 254) {
        emb[t] = 0.0f;
    }
    // piggyback: zero histogram (512*256 = 131072 >= CNT_PAD covered below)
    int bi = blockIdx.x * blockDim.x + t;
    if (bi < CNT_PAD) g_cnt[bi] = 0;
    __syncthreads();

    float s = bp[t];
    const float* w = Wp + (size_t)t * DIM;
#pragma unroll 8
    for (int k = 0; k < DIM; ++k) s += emb[k] * w[k];
    g_gating[p * DIM + t] = 2.0f / (1.0f + expf(-s));
}

// ---------------- counting sort: histogram ----------------------------------
__global__ void hist_kernel(const int* __restrict__ edges) {
    int e = blockIdx.x * blockDim.x + threadIdx.x;
    if (e >= TOTAL_EDGES) return;
    int tgt = edges[(size_t)2 * e + 1];
    atomicAdd(&g_cnt[tgt], 1);
}

// ---------------- counting sort: exclusive scan (single block) --------------
__global__ void scan_kernel() {
    __shared__ int part[SCAN_T];
    int t = threadIdx.x;
    int base = t * SCAN_CHUNK;
    int sum = 0;
#pragma unroll 7
    for (int j = 0; j < SCAN_CHUNK; ++j) {
        int idx = base + j;
        if (idx < N_NODES) sum += g_cnt[idx];
    }
    part[t] = sum;
    __syncthreads();
    for (int off = 1; off < SCAN_T; off <<= 1) {
        int v = (t >= off) ? part[t - off] : 0;
        __syncthreads();
        part[t] += v;
        __syncthreads();
    }
    int run = (t > 0) ? part[t - 1] : 0;
    for (int j = 0; j < SCAN_CHUNK; ++j) {
        int idx = base + j;
        if (idx < N_NODES) {
            g_off[idx] = run;
            g_cur[idx] = run;
            run += g_cnt[idx];
        }
    }
    if (t == SCAN_T - 1) g_off[N_NODES] = part[SCAN_T - 1];
}

// ---------------- counting sort: placement ----------------------------------
__global__ void place_kernel(const int* __restrict__ edges,
                             const int* __restrict__ posl) {
    int e = blockIdx.x * blockDim.x + threadIdx.x;
    if (e >= TOTAL_EDGES) return;
    int src  = edges[(size_t)2 * e];
    int tgt  = edges[(size_t)2 * e + 1];
    int pos  = posl[e];
    int type = e / M_PER_TYPE;
    int p = atomicAdd(&g_cur[tgt], 1);
    g_sorted[p] = ((uint32_t)src << 12) | ((uint32_t)type << 9) | (uint32_t)pos;
}

// ---------------- GEMM: prop = node_states @ W^T + b (3x bf16 mma) ---------
__device__ __forceinline__ void split_pack(float x, float y,
                                           uint32_t& hi, uint32_t& lo) {
    __nv_bfloat16 hx = __float2bfloat16_rn(x);
    __nv_bfloat16 hy = __float2bfloat16_rn(y);
    __nv_bfloat16 lx = __float2bfloat16_rn(x - __bfloat162float(hx));
    __nv_bfloat16 ly = __float2bfloat16_rn(y - __bfloat162float(hy));
    hi = ((uint32_t)__bfloat16_as_ushort(hy) << 16) | __bfloat16_as_ushort(hx);
    lo = ((uint32_t)__bfloat16_as_ushort(ly) << 16) | __bfloat16_as_ushort(lx);
}

__device__ __forceinline__ void mma16(float* d, const uint32_t* a, const uint32_t* b) {
    asm volatile(
        "mma.sync.aligned.m16n8k16.row.col.f32.bf16.bf16.f32 "
        "{%0,%1,%2,%3}, {%4,%5,%6,%7}, {%8,%9}, {%0,%1,%2,%3};"
        : "+f"(d[0]), "+f"(d[1]), "+f"(d[2]), "+f"(d[3])
        : "r"(a[0]), "r"(a[1]), "r"(a[2]), "r"(a[3]), "r"(b[0]), "r"(b[1]));
}

__global__ __launch_bounds__(256, 2)
void gemm_kernel(const float* __restrict__ A, const float* __restrict__ W,
                 const float* __restrict__ bias) {
    __shared__ __nv_bfloat16 Ah[128][40], Al[128][40];
    __shared__ __nv_bfloat16 Bh[64][40],  Bl[64][40];
    const int tid  = threadIdx.x;
    const int lane = tid & 31;
    const int wid  = tid >> 5;
    const int wm   = (wid & 3) * 32;
    const int wn   = (wid >> 2) * 32;
    const int mBase = blockIdx.y * 128;
    const int nBase = blockIdx.x * 64;

    float acc[2][4][4];
#pragma unroll
    for (int i = 0; i < 2; i++)
#pragma unroll
        for (int j = 0; j < 4; j++)
#pragma unroll
            for (int k = 0; k < 4; k++) acc[i][j][k] = 0.f;

    for (int k0 = 0; k0 < DIM; k0 += 32) {
#pragma unroll
        for (int i = tid; i < 128 * 8; i += 256) {
            int r = i >> 3, c4 = (i & 7) * 4;
            int gr = mBase + r;
            float4 v = make_float4(0.f, 0.f, 0.f, 0.f);
            if (gr < N_NODES)
                v = *reinterpret_cast<const float4*>(A + (size_t)gr * DIM + k0 + c4);
            uint32_t h01, l01, h23, l23;
            split_pack(v.x, v.y, h01, l01);
            split_pack(v.z, v.w, h23, l23);
            *reinterpret_cast<uint32_t*>(&Ah[r][c4])     = h01;
            *reinterpret_cast<uint32_t*>(&Ah[r][c4 + 2]) = h23;
            *reinterpret_cast<uint32_t*>(&Al[r][c4])     = l01;
            *reinterpret_cast<uint32_t*>(&Al[r][c4 + 2]) = l23;
        }
#pragma unroll
        for (int i = tid; i < 64 * 8; i += 256) {
            int r = i >> 3, c4 = (i & 7) * 4;
            float4 v = *reinterpret_cast<const float4*>(
                W + (size_t)(nBase + r) * DIM + k0 + c4);
            uint32_t h01, l01, h23, l23;
            split_pack(v.x, v.y, h01, l01);
            split_pack(v.z, v.w, h23, l23);
            *reinterpret_cast<uint32_t*>(&Bh[r][c4])     = h01;
            *reinterpret_cast<uint32_t*>(&Bh[r][c4 + 2]) = h23;
            *reinterpret_cast<uint32_t*>(&Bl[r][c4])     = l01;
            *reinterpret_cast<uint32_t*>(&Bl[r][c4 + 2]) = l23;
        }
        __syncthreads();

#pragma unroll
        for (int kk = 0; kk < 32; kk += 16) {
            const int cA = kk + (lane & 3) * 2;
            uint32_t ah[2][4], al[2][4];
#pragma unroll
            for (int mt = 0; mt < 2; mt++) {
                int r0 = wm + mt * 16 + (lane >> 2);
                ah[mt][0] = *reinterpret_cast<const uint32_t*>(&Ah[r0][cA]);
                ah[mt][1] = *reinterpret_cast<const uint32_t*>(&Ah[r0 + 8][cA]);
                ah[mt][2] = *reinterpret_cast<const uint32_t*>(&Ah[r0][cA + 8]);
                ah[mt][3] = *reinterpret_cast<const uint32_t*>(&Ah[r0 + 8][cA + 8]);
                al[mt][0] = *reinterpret_cast<const uint32_t*>(&Al[r0][cA]);
                al[mt][1] = *reinterpret_cast<const uint32_t*>(&Al[r0 + 8][cA]);
                al[mt][2] = *reinterpret_cast<const uint32_t*>(&Al[r0][cA + 8]);
                al[mt][3] = *reinterpret_cast<const uint32_t*>(&Al[r0 + 8][cA + 8]);
            }
            uint32_t bh[4][2], bl[4][2];
#pragma unroll
            for (int nt = 0; nt < 4; nt++) {
                int n0 = wn + nt * 8 + (lane >> 2);
                bh[nt][0] = *reinterpret_cast<const uint32_t*>(&Bh[n0][cA]);
                bh[nt][1] = *reinterpret_cast<const uint32_t*>(&Bh[n0][cA + 8]);
                bl[nt][0] = *reinterpret_cast<const uint32_t*>(&Bl[n0][cA]);
                bl[nt][1] = *reinterpret_cast<const uint32_t*>(&Bl[n0][cA + 8]);
            }
#pragma unroll
            for (int mt = 0; mt < 2; mt++)
#pragma unroll
                for (int nt = 0; nt < 4; nt++) {
                    mma16(acc[mt][nt], ah[mt], bh[nt]);
                    mma16(acc[mt][nt], ah[mt], bl[nt]);
                    mma16(acc[mt][nt], al[mt], bh[nt]);
                }
        }
        __syncthreads();
    }

#pragma unroll
    for (int mt = 0; mt < 2; mt++) {
#pragma unroll
        for (int nt = 0; nt < 4; nt++) {
            int row = mBase + wm + mt * 16 + (lane >> 2);
            int col = nBase + wn + nt * 8 + 2 * (lane & 3);
            float b0 = bias[col], b1 = bias[col + 1];
            if (row < N_NODES) {
                float2 v = make_float2(acc[mt][nt][0] + b0, acc[mt][nt][1] + b1);
                *reinterpret_cast<float2*>(&g_prop[(size_t)row * NBIG + col]) = v;
            }
            if (row + 8 < N_NODES) {
                float2 v = make_float2(acc[mt][nt][2] + b0, acc[mt][nt][3] + b1);
                *reinterpret_cast<float2*>(&g_prop[(size_t)(row + 8) * NBIG + col]) = v;
            }
        }
    }
}

// ---------------- message: warp per target, register accumulation ----------
__global__ __launch_bounds__(256)
void message_kernel(float* __restrict__ out) {
    int t    = (blockIdx.x * blockDim.x + threadIdx.x) >> 5;
    int lane = threadIdx.x & 31;
    if (t >= N_NODES) return;

    const int s0 = g_off[t];
    const int s1 = g_off[t + 1];

    float4 a0 = make_float4(0.f, 0.f, 0.f, 0.f);
    float4 a1 = make_float4(0.f, 0.f, 0.f, 0.f);

    uint32_t pk = (s0 < s1) ? g_sorted[s0] : 0u;
    for (int e = s0; e < s1; ++e) {
        uint32_t cur = pk;
        if (e + 1 < s1) pk = g_sorted[e + 1];   // prefetch next packed record

        int src  = cur >> 12;
        int type = (cur >> 9) & 7;
        int pos  = cur & 511;

        const float4* __restrict__ p = reinterpret_cast<const float4*>(
            g_prop + (size_t)src * NBIG + type * DIM) + lane * 2;
        const float4* g = reinterpret_cast<const float4*>(
            g_gating + (size_t)pos * DIM) + lane * 2;
        float4 p0 = p[0], p1 = p[1];
        float4 g0 = __ldg(g), g1 = __ldg(g + 1);
        a0.x += p0.x * g0.x; a0.y += p0.y * g0.y;
        a0.z += p0.z * g0.z; a0.w += p0.w * g0.w;
        a1.x += p1.x * g1.x; a1.y += p1.y * g1.y;
        a1.z += p1.z * g1.z; a1.w += p1.w * g1.w;
    }

    int deg = s1 - s0;
    float div = ((deg == 0) ? 1.0f : (float)deg) + 1e-8f;
    float s = 1.0f / div;
    a0.x *= s; a0.y *= s; a0.z *= s; a0.w *= s;
    a1.x *= s; a1.y *= s; a1.z *= s; a1.w *= s;

    float4* dst = reinterpret_cast<float4*>(out + (size_t)t * DIM) + lane * 2;
    dst[0] = a0;
    dst[1] = a1;
}

// ---------------- launch ----------------------------------------------------
extern "C" void kernel_launch(void* const* d_in, const int* in_sizes, int n_in,
                              void* d_out, int out_size) {
    const float* node_states = (const float*)d_in[0];
    const float* W    = (const float*)d_in[1];
    const float* b    = (const float*)d_in[2];
    const float* Wp   = (const float*)d_in[3];
    const float* bp   = (const float*)d_in[4];
    const int*   edges = (const int*)d_in[5];
    const int*   posl  = (const int*)d_in[6];
    float* out = (float*)d_out;

    gating_kernel<<<POS_TAB, 256>>>(Wp, bp);                       // + zero hist
    hist_kernel<<<(TOTAL_EDGES + 255) / 256, 256>>>(edges);
    scan_kernel<<<1, SCAN_T>>>();
    place_kernel<<<(TOTAL_EDGES + 255) / 256, 256>>>(edges, posl);

    dim3 gg(NBIG / 64, (N_NODES + 127) / 128);
    gemm_kernel<<<gg, 256>>>(node_states, W, b);

    message_kernel<<<(N_NODES * 32 + 255) / 256, 256>>>(out);
}